// round 6
// baseline (speedup 1.0000x reference)
#include <cuda_runtime.h>
#include <cstdint>

#define BB   16
#define C_IN 256
#define CRr  128
#define KKGc 144
#define HWn  3136
#define HH   56
#define WWc  56

typedef unsigned long long ull;

// ---------------- scratch (allocation-free: __device__ globals) ----------------
__device__ float g_t[(size_t)BB * CRr * HWn];     // reduce-conv output  [b][cr][hw]
__device__ float g_kern[(size_t)BB * KKGc * HWn]; // span-conv output    [b][o][hw]
__device__ float g_scale[CRr];
__device__ float g_shift[CRr];

// ---------------- packed fp32x2 helpers ----------------
__device__ __forceinline__ ull dup2(float x) {
    ull r;
    asm("mov.b64 %0, {%1, %1};" : "=l"(r) : "f"(x));
    return r;
}
__device__ __forceinline__ void fma2(ull& acc, ull a, ull b) {
    asm("fma.rn.f32x2 %0, %1, %2, %0;" : "+l"(acc) : "l"(a), "l"(b));
}
__device__ __forceinline__ void unpack2(ull v, float& lo, float& hi) {
    asm("mov.b64 {%0, %1}, %2;" : "=f"(lo), "=f"(hi) : "l"(v));
}

// ---------------------------------------------------------------------------
// Tiled fp32 GEMM (f32x2-packed, M-paired accumulators, B pre-duplicated in
// smem, double-buffered single-sync pipeline). Per batch z:
//   C[m][n] = sum_k A[m][k] * Bin[k][n] + bias[m]
// SPAN=true : Bin = relu(g_t * scale + shift), Cout = g_kern   (K=128, M=144)
// SPAN=false: Bin = X,                         Cout = g_t      (K=256, M=128)
// ---------------------------------------------------------------------------
template<int M, int K, bool SPAN>
__global__ __launch_bounds__(256)
void gemm_k(const float* __restrict__ A,
            const float* __restrict__ bias,
            const float* __restrict__ X)
{
    constexpr int BM = 128, BN = 128, BK = 16, TM = 8, TN = 8;
    __shared__ __align__(16) float As[2][BK][BM + 4];
    __shared__ __align__(16) ull   Bs[2][BK][BN];   // each entry = {v, v}

    const int b   = blockIdx.z;
    const int n0  = blockIdx.x * BN;
    const int m0  = blockIdx.y * BM;
    const int tid = threadIdx.x;
    const int tx  = tid & 15;   // N dim (8 cols)
    const int ty  = tid >> 4;   // M dim (4 m-pairs)

    const float* Bin  = SPAN ? (g_t    + (size_t)b * K * HWn) : (X   + (size_t)b * K * HWn);
    float*       Cout = SPAN ? (g_kern + (size_t)b * M * HWn) : (g_t + (size_t)b * M * HWn);

    // warp-aligned skip for the partial M block (M=144: block y=1 -> 16 live rows)
    bool active = true;
    if constexpr (M % BM != 0) active = (m0 + ty * TM) < M;

    ull acc2[TM / 2][TN] = {};   // [m-pair][n], packed {row m, row m+1}

    // ---- global->reg load lambdas (manually inlined as macel) ----
    const int arow = tid >> 1;          // 0..127 (m within tile)
    const int ak   = (tid & 1) * 8;     // 0 or 8 (k offset)

    float  aReg[8];
    float4 bReg[2];
    int    bCol[2], bRow[2];

    auto loadA = [&](int k0) {
        const int grow = m0 + arow;
        bool ok = true;
        if constexpr (M % BM != 0) ok = (grow < M);
        if (ok) {
            const float* ap = A + (size_t)grow * K + k0 + ak;
            float4 v0 = *reinterpret_cast<const float4*>(ap);
            float4 v1 = *reinterpret_cast<const float4*>(ap + 4);
            aReg[0]=v0.x; aReg[1]=v0.y; aReg[2]=v0.z; aReg[3]=v0.w;
            aReg[4]=v1.x; aReg[5]=v1.y; aReg[6]=v1.z; aReg[7]=v1.w;
        } else {
            #pragma unroll
            for (int i = 0; i < 8; i++) aReg[i] = 0.f;
        }
    };
    auto loadB = [&](int k0) {
        #pragma unroll
        for (int it = 0; it < 2; it++) {
            const int lin  = tid + it * 256;
            bRow[it] = lin >> 5;            // 0..15
            const int bc4  = lin & 31;      // 0..31
            bCol[it] = bc4 * 4;
            const int col  = n0 + bc4 * 4;
            float4 v;
            if (col < HWn) {
                v = *reinterpret_cast<const float4*>(Bin + (size_t)(k0 + bRow[it]) * HWn + col);
                if constexpr (SPAN) {
                    const int c   = k0 + bRow[it];
                    const float sc = g_scale[c], sh = g_shift[c];
                    v.x = fmaxf(fmaf(v.x, sc, sh), 0.f);
                    v.y = fmaxf(fmaf(v.y, sc, sh), 0.f);
                    v.z = fmaxf(fmaf(v.z, sc, sh), 0.f);
                    v.w = fmaxf(fmaf(v.w, sc, sh), 0.f);
                }
            } else {
                v = make_float4(0.f, 0.f, 0.f, 0.f);
            }
            bReg[it] = v;
        }
    };
    auto storeTile = [&](int buf) {
        As[buf][ak + 0][arow] = aReg[0]; As[buf][ak + 1][arow] = aReg[1];
        As[buf][ak + 2][arow] = aReg[2]; As[buf][ak + 3][arow] = aReg[3];
        As[buf][ak + 4][arow] = aReg[4]; As[buf][ak + 5][arow] = aReg[5];
        As[buf][ak + 6][arow] = aReg[6]; As[buf][ak + 7][arow] = aReg[7];
        #pragma unroll
        for (int it = 0; it < 2; it++) {
            ull* bp = &Bs[buf][bRow[it]][bCol[it]];
            bp[0] = dup2(bReg[it].x);
            bp[1] = dup2(bReg[it].y);
            bp[2] = dup2(bReg[it].z);
            bp[3] = dup2(bReg[it].w);
        }
    };

    // ---- prologue: tile 0 ----
    loadA(0); loadB(0);
    storeTile(0);
    __syncthreads();

    int buf = 0;
    for (int k0 = 0; k0 < K; k0 += BK) {
        const bool more = (k0 + BK) < K;
        if (more) { loadA(k0 + BK); loadB(k0 + BK); }

        if (active) {
            #pragma unroll
            for (int k = 0; k < BK; k++) {
                // A m-pairs: 4 x 64-bit packed {m, m+1} straight from smem
                const ulonglong2* ap =
                    reinterpret_cast<const ulonglong2*>(&As[buf][k][ty * TM]);
                ulonglong2 a01 = ap[0], a23 = ap[1];
                ull a2[4] = { a01.x, a01.y, a23.x, a23.y };
                // B duplicated pairs: 8 x {b, b}
                const ulonglong2* bp =
                    reinterpret_cast<const ulonglong2*>(&Bs[buf][k][tx * TN]);
                ulonglong2 b01 = bp[0], b23 = bp[1], b45 = bp[2], b67 = bp[3];
                ull b2[8] = { b01.x, b01.y, b23.x, b23.y, b45.x, b45.y, b67.x, b67.y };
                #pragma unroll
                for (int i = 0; i < TM / 2; i++)
                    #pragma unroll
                    for (int j = 0; j < TN; j++)
                        fma2(acc2[i][j], a2[i], b2[j]);
            }
        }

        if (more) {
            storeTile(buf ^ 1);
            __syncthreads();
            buf ^= 1;
        }
    }

    // ---- store (+bias) ----
    const int colb = n0 + tx * TN;
    if (active && colb < HWn) {
        #pragma unroll
        for (int i = 0; i < TM / 2; i++) {
            float lo[TN], hi[TN];
            #pragma unroll
            for (int j = 0; j < TN; j++) unpack2(acc2[i][j], lo[j], hi[j]);
            #pragma unroll
            for (int half = 0; half < 2; half++) {
                const int grow = m0 + ty * TM + 2 * i + half;
                bool ok = true;
                if constexpr (M % BM != 0) ok = (grow < M);
                if (ok) {
                    const float* src = half ? hi : lo;
                    const float bv = bias[grow];
                    float4 o0, o1;
                    o0.x = src[0] + bv; o0.y = src[1] + bv;
                    o0.z = src[2] + bv; o0.w = src[3] + bv;
                    o1.x = src[4] + bv; o1.y = src[5] + bv;
                    o1.z = src[6] + bv; o1.w = src[7] + bv;
                    float* cp = Cout + (size_t)grow * HWn + colb;
                    *reinterpret_cast<float4*>(cp)     = o0;
                    *reinterpret_cast<float4*>(cp + 4) = o1;
                }
            }
        }
    }
}

// ---------------------------------------------------------------------------
// BatchNorm statistics (deterministic fixed-order tree reduction).
// ---------------------------------------------------------------------------
__global__ __launch_bounds__(1024)
void bn_stats(const float* __restrict__ gamma, const float* __restrict__ beta)
{
    const int c   = blockIdx.x;
    const int tid = threadIdx.x;
    float s = 0.f, sq = 0.f;
    for (int b = 0; b < BB; b++) {
        const float* p = g_t + ((size_t)b * CRr + c) * HWn;
        for (int i = tid; i < HWn; i += 1024) {
            float v = p[i];
            s  += v;
            sq  = fmaf(v, v, sq);
        }
    }
    __shared__ float ss[1024], sqs[1024];
    ss[tid] = s; sqs[tid] = sq;
    __syncthreads();
    for (int o = 512; o > 0; o >>= 1) {
        if (tid < o) { ss[tid] += ss[tid + o]; sqs[tid] += sqs[tid + o]; }
        __syncthreads();
    }
    if (tid == 0) {
        const float inv  = 1.f / (float)(BB * HWn);
        const float mean = ss[0] * inv;
        const float var  = sqs[0] * inv - mean * mean;
        const float rstd = rsqrtf(var + 1e-5f);
        const float sc   = gamma[c] * rstd;
        g_scale[c] = sc;
        g_shift[c] = beta[c] - mean * sc;
    }
}

// ---------------------------------------------------------------------------
// Involution gather, d-pair packed (f32x2). x tile staged d-innermost so a
// d-pair is one 8-byte LDS; taps duplicated once into registers.
//   out[b, g*16+d, h, w] = sum_{i,j} x[b, g*16+d, h+i-1, w+j-1]
//                              * kern[b, (i*3+j)*16+g, h, w]
// ---------------------------------------------------------------------------
#define THT 4
#define DPAD 18   // 16 d + pad 2: keeps pairs 8B-aligned, 2-way conflicts max
__global__ __launch_bounds__(224)
void involution_kernel(const float* __restrict__ x, float* __restrict__ out)
{
    __shared__ __align__(16) float sx[THT + 2][60][DPAD]; // [row][col(halo)][d]
    __shared__ float skn[9][THT][WWc];

    const int h0  = blockIdx.x * THT;
    const int g   = blockIdx.y;
    const int b   = blockIdx.z;
    const int tid = threadIdx.x;            // 0..223

    // ---- stage x tile transposed: d innermost ----
    const float* xg = x + ((size_t)b * C_IN + g * 16) * HWn;
    for (int idx = tid; idx < 16 * (THT + 2) * 58; idx += 224) {
        const int d    = idx / ((THT + 2) * 58);
        const int rem  = idx - d * ((THT + 2) * 58);
        const int r    = rem / 58;
        const int cpos = rem - r * 58;
        const int hh   = h0 - 1 + r;
        const int ww   = cpos - 1;
        float v = 0.f;
        if (hh >= 0 && hh < HH && ww >= 0 && ww < WWc)
            v = xg[(size_t)d * HWn + hh * WWc + ww];
        sx[r][cpos][d] = v;
    }
    // ---- stage kernel slice: 9 taps x THT rows x 56 ----
    const float* kg = g_kern + ((size_t)b * KKGc + g) * HWn + h0 * WWc;
    for (int idx = tid; idx < 9 * THT * WWc; idx += 224) {
        const int t  = idx / (THT * WWc);
        const int r  = (idx / WWc) % THT;
        const int ww = idx % WWc;
        skn[t][r][ww] = kg[(size_t)t * 16 * HWn + r * WWc + ww];
    }
    __syncthreads();

    const int w  = tid % WWc;
    const int hl = tid / WWc;   // 0..3

    ull kv2[9];
    #pragma unroll
    for (int t = 0; t < 9; t++) kv2[t] = dup2(skn[t][hl][w]);

    const float* sbase = &sx[hl][w][0];
    float* og = out + ((size_t)b * C_IN + g * 16) * HWn + (h0 + hl) * WWc + w;

    #pragma unroll
    for (int dp = 0; dp < 8; dp++) {
        ull acc = 0;
        #pragma unroll
        for (int i = 0; i < 3; i++)
            #pragma unroll
            for (int j = 0; j < 3; j++) {
                const ull xv = *reinterpret_cast<const ull*>(
                    sbase + ((i * 60 + j) * DPAD + 2 * dp));
                fma2(acc, xv, kv2[i * 3 + j]);
            }
        float lo, hi;
        unpack2(acc, lo, hi);
        og[(size_t)(2 * dp)     * HWn] = lo;
        og[(size_t)(2 * dp + 1) * HWn] = hi;
    }
}

// ---------------------------------------------------------------------------
extern "C" void kernel_launch(void* const* d_in, const int* in_sizes, int n_in,
                              void* d_out, int out_size)
{
    (void)in_sizes; (void)n_in; (void)out_size;
    const float* x        = (const float*)d_in[0];
    const float* w_reduce = (const float*)d_in[1];
    const float* b_reduce = (const float*)d_in[2];
    const float* gamma    = (const float*)d_in[3];
    const float* beta     = (const float*)d_in[4];
    const float* w_span   = (const float*)d_in[5];
    const float* b_span   = (const float*)d_in[6];
    float* out = (float*)d_out;

    // 1) reduce conv:  t = w_reduce @ x + b_reduce
    dim3 g1((HWn + 127) / 128, 1, BB);
    gemm_k<CRr, C_IN, false><<<g1, 256>>>(w_reduce, b_reduce, x);

    // 2) BN batch statistics -> folded scale/shift
    bn_stats<<<CRr, 1024>>>(gamma, beta);

    // 3) span conv with fused BN+ReLU: kern = w_span @ relu(bn(t)) + b_span
    dim3 g2((HWn + 127) / 128, (KKGc + 127) / 128, BB);
    gemm_k<KKGc, CRr, true><<<g2, 256>>>(w_span, b_span, nullptr);

    // 4) involution gather
    dim3 g3(HH / THT, 16, BB);
    involution_kernel<<<g3, 224>>>(x, out);
}

// round 7
// speedup vs baseline: 2.3001x; 2.3001x over previous
#include <cuda_runtime.h>
#include <cstdint>

#define BB   16
#define C_IN 256
#define CRr  128
#define KKGc 144
#define HWn  3136
#define HH   56
#define WWc  56

typedef unsigned long long ull;

// ---------------- scratch (allocation-free: __device__ globals) ----------------
__device__ float g_t[(size_t)BB * CRr * HWn];     // reduce-conv output  [b][cr][hw]
__device__ float g_kern[(size_t)BB * KKGc * HWn]; // span-conv output    [b][o][hw]
__device__ float g_scale[CRr];
__device__ float g_shift[CRr];
__device__ float g_bns[CRr][BB];                  // partial sums
__device__ float g_bnq[CRr][BB];                  // partial sumsq

// ---------------- packed fp32x2 helpers ----------------
__device__ __forceinline__ ull dup2(float x) {
    ull r;
    asm("mov.b64 %0, {%1, %1};" : "=l"(r) : "f"(x));
    return r;
}
__device__ __forceinline__ void fma2(ull& acc, ull a, ull b) {
    asm("fma.rn.f32x2 %0, %1, %2, %0;" : "+l"(acc) : "l"(a), "l"(b));
}
__device__ __forceinline__ void unpack2(ull v, float& lo, float& hi) {
    asm("mov.b64 {%0, %1}, %2;" : "=f"(lo), "=f"(hi) : "l"(v));
}

// ---------------------------------------------------------------------------
// Tiled fp32 GEMM (f32x2-packed, R3-proven inner loop; BK=32 with
// register-staged single-smem-buffer pipeline). Per batch z:
//   C[m][n] = sum_k A[m][k] * Bin[k][n] + bias[m]
// SPAN=true : Bin = relu(g_t * scale + shift), Cout = g_kern   (K=128, M=144)
// SPAN=false: Bin = X,                         Cout = g_t      (K=256, M=128)
// ---------------------------------------------------------------------------
template<int M, int K, bool SPAN>
__global__ __launch_bounds__(256)
void gemm_k(const float* __restrict__ A,
            const float* __restrict__ bias,
            const float* __restrict__ X)
{
    constexpr int BM = 128, BN = 128, BK = 32, TM = 8, TN = 8;
    __shared__ __align__(16) float As[BK][BM + 4];
    __shared__ __align__(16) float Bs[BK][BN];

    const int b   = blockIdx.z;
    const int n0  = blockIdx.x * BN;
    const int m0  = blockIdx.y * BM;
    const int tid = threadIdx.x;
    const int tx  = tid & 15;   // N dim
    const int ty  = tid >> 4;   // M dim

    const float* Bin  = SPAN ? (g_t    + (size_t)b * K * HWn) : (X   + (size_t)b * K * HWn);
    float*       Cout = SPAN ? (g_kern + (size_t)b * M * HWn) : (g_t + (size_t)b * M * HWn);

    // warp-aligned skip for the partial M block (M=144: block y=1 -> 16 live rows)
    bool active = true;
    if constexpr (M % BM != 0) active = (m0 + ty * TM) < M;

    ull acc2[TM][TN / 2] = {};   // [m][n-pair], packed {n, n+1}

    // ---- load mappings ----
    const int arow = tid >> 1;          // 0..127 (m within tile)
    const int ak   = (tid & 1) * 16;    // 0 or 16 (k offset, 16 floats each)

    float4 aReg[4];
    float4 bReg[4];

    auto loadRegs = [&](int k0) {
        // A: one row segment of 16 floats
        const int grow = m0 + arow;
        bool ok = true;
        if constexpr (M % BM != 0) ok = (grow < M);
        if (ok) {
            const float* ap = A + (size_t)grow * K + k0 + ak;
            #pragma unroll
            for (int i = 0; i < 4; i++)
                aReg[i] = *reinterpret_cast<const float4*>(ap + 4 * i);
        } else {
            #pragma unroll
            for (int i = 0; i < 4; i++) aReg[i] = make_float4(0.f, 0.f, 0.f, 0.f);
        }
        // B: 4 float4 slots, fused BN+ReLU for SPAN
        #pragma unroll
        for (int it = 0; it < 4; it++) {
            const int lin  = tid + it * 256;     // 0..1023
            const int brow = lin >> 5;           // 0..31
            const int bc4  = lin & 31;           // 0..31
            const int col  = n0 + bc4 * 4;
            float4 v;
            if (col < HWn) {
                v = *reinterpret_cast<const float4*>(Bin + (size_t)(k0 + brow) * HWn + col);
                if constexpr (SPAN) {
                    const int c   = k0 + brow;
                    const float sc = g_scale[c], sh = g_shift[c];
                    v.x = fmaxf(fmaf(v.x, sc, sh), 0.f);
                    v.y = fmaxf(fmaf(v.y, sc, sh), 0.f);
                    v.z = fmaxf(fmaf(v.z, sc, sh), 0.f);
                    v.w = fmaxf(fmaf(v.w, sc, sh), 0.f);
                }
            } else {
                v = make_float4(0.f, 0.f, 0.f, 0.f);
            }
            bReg[it] = v;
        }
    };
    auto storeSmem = [&]() {
        #pragma unroll
        for (int i = 0; i < 4; i++) {
            As[ak + 4 * i + 0][arow] = aReg[i].x;
            As[ak + 4 * i + 1][arow] = aReg[i].y;
            As[ak + 4 * i + 2][arow] = aReg[i].z;
            As[ak + 4 * i + 3][arow] = aReg[i].w;
        }
        #pragma unroll
        for (int it = 0; it < 4; it++) {
            const int lin  = tid + it * 256;
            const int brow = lin >> 5;
            const int bc4  = lin & 31;
            *reinterpret_cast<float4*>(&Bs[brow][bc4 * 4]) = bReg[it];
        }
    };

    // ---- prologue ----
    loadRegs(0);
    storeSmem();
    __syncthreads();

    for (int k0 = 0; k0 < K; k0 += BK) {
        const bool more = (k0 + BK) < K;
        if (more) loadRegs(k0 + BK);   // LDGs overlap the compute below

        if (active) {
            #pragma unroll 8
            for (int k = 0; k < BK; k++) {
                float4 a0 = *reinterpret_cast<const float4*>(&As[k][ty * TM]);
                float4 a1 = *reinterpret_cast<const float4*>(&As[k][ty * TM + 4]);
                ull ad[TM];
                ad[0] = dup2(a0.x); ad[1] = dup2(a0.y);
                ad[2] = dup2(a0.z); ad[3] = dup2(a0.w);
                ad[4] = dup2(a1.x); ad[5] = dup2(a1.y);
                ad[6] = dup2(a1.z); ad[7] = dup2(a1.w);
                const ull* bp = reinterpret_cast<const ull*>(&Bs[k][tx * TN]);
                ull b2[4];
                b2[0] = bp[0]; b2[1] = bp[1]; b2[2] = bp[2]; b2[3] = bp[3];
                #pragma unroll
                for (int i = 0; i < TM; i++)
                    #pragma unroll
                    for (int j = 0; j < TN / 2; j++)
                        fma2(acc2[i][j], ad[i], b2[j]);
            }
        }

        if (more) {
            __syncthreads();   // everyone done reading current tile
            storeSmem();
            __syncthreads();   // next tile visible
        }
    }

    // ---- store (+bias) ----
    const int colb = n0 + tx * TN;
    if (active && colb < HWn) {
        #pragma unroll
        for (int i = 0; i < TM; i++) {
            const int grow = m0 + ty * TM + i;
            bool ok = true;
            if constexpr (M % BM != 0) ok = (grow < M);
            if (ok) {
                const float bv = bias[grow];
                float o[TN];
                #pragma unroll
                for (int j = 0; j < TN / 2; j++)
                    unpack2(acc2[i][j], o[2 * j], o[2 * j + 1]);
                float4 o0, o1;
                o0.x = o[0] + bv; o0.y = o[1] + bv; o0.z = o[2] + bv; o0.w = o[3] + bv;
                o1.x = o[4] + bv; o1.y = o[5] + bv; o1.z = o[6] + bv; o1.w = o[7] + bv;
                float* cp = Cout + (size_t)grow * HWn + colb;
                *reinterpret_cast<float4*>(cp)     = o0;
                *reinterpret_cast<float4*>(cp + 4) = o1;
            }
        }
    }
}

// ---------------------------------------------------------------------------
// BatchNorm stats, two-stage deterministic reduction.
// Stage 1: per (channel, batch) plane -> partial sum/sumsq.
// Stage 2: one block folds 16 partials per channel with gamma/beta.
// ---------------------------------------------------------------------------
__global__ __launch_bounds__(256)
void bn_partial()
{
    const int c   = blockIdx.x;
    const int b   = blockIdx.y;
    const int tid = threadIdx.x;
    const float4* p = reinterpret_cast<const float4*>(
        g_t + ((size_t)b * CRr + c) * HWn);
    float s = 0.f, sq = 0.f;
    for (int i = tid; i < HWn / 4; i += 256) {
        float4 v = p[i];
        s += v.x + v.y + v.z + v.w;
        sq = fmaf(v.x, v.x, sq); sq = fmaf(v.y, v.y, sq);
        sq = fmaf(v.z, v.z, sq); sq = fmaf(v.w, v.w, sq);
    }
    __shared__ float ss[256], sqs[256];
    ss[tid] = s; sqs[tid] = sq;
    __syncthreads();
    for (int o = 128; o > 0; o >>= 1) {
        if (tid < o) { ss[tid] += ss[tid + o]; sqs[tid] += sqs[tid + o]; }
        __syncthreads();
    }
    if (tid == 0) { g_bns[c][b] = ss[0]; g_bnq[c][b] = sqs[0]; }
}

__global__ __launch_bounds__(CRr)
void bn_finalize(const float* __restrict__ gamma, const float* __restrict__ beta)
{
    const int c = threadIdx.x;
    float s = 0.f, sq = 0.f;
    #pragma unroll
    for (int b = 0; b < BB; b++) { s += g_bns[c][b]; sq += g_bnq[c][b]; }
    const float inv  = 1.f / (float)(BB * HWn);
    const float mean = s * inv;
    const float var  = sq * inv - mean * mean;
    const float rstd = rsqrtf(var + 1e-5f);
    const float sc   = gamma[c] * rstd;
    g_scale[c] = sc;
    g_shift[c] = beta[c] - mean * sc;
}

// ---------------------------------------------------------------------------
// Involution gather. Block = (h_tile of 8 rows, g, b), 448 threads.
// x tile staged in smem with zero-filled halo (cheap indexing: <=2 divisions
// per thread); kernel taps read straight from gmem into registers (coalesced).
//   out[b, g*16+d, h, w] = sum_{i,j} x[b, g*16+d, h+i-1, w+j-1]
//                              * kern[b, (i*3+j)*16+g, h, w]
// ---------------------------------------------------------------------------
#define THT 8
__global__ __launch_bounds__(448)
void involution_kernel(const float* __restrict__ x, float* __restrict__ out)
{
    __shared__ float sx[16][THT + 2][58];   // [d][row(halo)][col(halo)]

    const int h0  = blockIdx.x * THT;
    const int g   = blockIdx.y;
    const int b   = blockIdx.z;
    const int tid = threadIdx.x;            // 0..447

    const int w = tid % WWc;                // 0..55
    const int q = tid / WWc;                // 0..7  (output row within tile)

    // ---- stage x tile: (THT+2) x 58 positions, all 16 d per position ----
    const float* xg = x + ((size_t)b * C_IN + g * 16) * HWn;
    for (int p = tid; p < (THT + 2) * 58; p += 448) {
        const int r    = p / 58;                       // <=2 divisions total
        const int cpos = p - r * 58;
        const int hh   = h0 - 1 + r;
        const int ww   = cpos - 1;
        const bool ok  = (hh >= 0) && (hh < HH) && (ww >= 0) && (ww < WWc);
        const float* src = xg + hh * WWc + ww;
        #pragma unroll
        for (int d = 0; d < 16; d++)
            sx[d][r][cpos] = ok ? src[(size_t)d * HWn] : 0.f;
    }

    // ---- kernel taps straight to registers (coalesced over w) ----
    const float* kg = g_kern + ((size_t)b * KKGc + g) * HWn + (h0 + q) * WWc + w;
    float kv[9];
    #pragma unroll
    for (int t = 0; t < 9; t++) kv[t] = kg[(size_t)t * 16 * HWn];

    __syncthreads();

    float* og = out + ((size_t)b * C_IN + g * 16) * HWn + (h0 + q) * WWc + w;
    #pragma unroll
    for (int d = 0; d < 16; d++) {
        float acc = 0.f;
        #pragma unroll
        for (int i = 0; i < 3; i++)
            #pragma unroll
            for (int j = 0; j < 3; j++)
                acc = fmaf(sx[d][q + i][w + j], kv[i * 3 + j], acc);
        og[(size_t)d * HWn] = acc;
    }
}

// ---------------------------------------------------------------------------
extern "C" void kernel_launch(void* const* d_in, const int* in_sizes, int n_in,
                              void* d_out, int out_size)
{
    (void)in_sizes; (void)n_in; (void)out_size;
    const float* x        = (const float*)d_in[0];
    const float* w_reduce = (const float*)d_in[1];
    const float* b_reduce = (const float*)d_in[2];
    const float* gamma    = (const float*)d_in[3];
    const float* beta     = (const float*)d_in[4];
    const float* w_span   = (const float*)d_in[5];
    const float* b_span   = (const float*)d_in[6];
    float* out = (float*)d_out;

    // 1) reduce conv:  t = w_reduce @ x + b_reduce
    dim3 g1((HWn + 127) / 128, 1, BB);
    gemm_k<CRr, C_IN, false><<<g1, 256>>>(w_reduce, b_reduce, x);

    // 2) BN batch statistics -> folded scale/shift (two-stage, deterministic)
    bn_partial<<<dim3(CRr, BB), 256>>>();
    bn_finalize<<<1, CRr>>>(gamma, beta);

    // 3) span conv with fused BN+ReLU: kern = w_span @ relu(bn(t)) + b_span
    dim3 g2((HWn + 127) / 128, (KKGc + 127) / 128, BB);
    gemm_k<KKGc, CRr, true><<<g2, 256>>>(w_span, b_span, nullptr);

    // 4) involution gather
    dim3 g3(HH / THT, 16, BB);
    involution_kernel<<<g3, 448>>>(x, out);
}

// round 8
// speedup vs baseline: 2.3443x; 1.0192x over previous
#include <cuda_runtime.h>
#include <cstdint>

#define BB   16
#define C_IN 256
#define CRr  128
#define KKGc 144
#define HWn  3136
#define HH   56
#define WWc  56

typedef unsigned long long ull;

// ---------------- scratch (allocation-free: __device__ globals) ----------------
__device__ float g_t[(size_t)BB * CRr * HWn];     // reduce-conv output  [b][cr][hw]
__device__ float g_kern[(size_t)BB * KKGc * HWn]; // span-conv output    [b][o][hw]
__device__ float g_scale[CRr];
__device__ float g_shift[CRr];
__device__ float g_bns[CRr][BB];                  // partial sums
__device__ float g_bnq[CRr][BB];                  // partial sumsq

// ---------------- packed fp32x2 helpers ----------------
__device__ __forceinline__ ull dup2(float x) {
    ull r;
    asm("mov.b64 %0, {%1, %1};" : "=l"(r) : "f"(x));
    return r;
}
__device__ __forceinline__ void fma2(ull& acc, ull a, ull b) {
    asm("fma.rn.f32x2 %0, %1, %2, %0;" : "+l"(acc) : "l"(a), "l"(b));
}
__device__ __forceinline__ void unpack2(ull v, float& lo, float& hi) {
    asm("mov.b64 {%0, %1}, %2;" : "=f"(lo), "=f"(hi) : "l"(v));
}

// ---------------------------------------------------------------------------
// Tiled fp32 GEMM (f32x2-packed, register-staged pipeline). M must be a
// multiple of 128 (no padding logic). Per batch z:
//   C[m][n] = sum_k A[m][k] * Bin[k][n] + bias[m]
// SPAN=true : Bin = relu(g_t * scale + shift), Cout = g_kern   (K=128)
// SPAN=false: Bin = X,                         Cout = g_t      (K=256)
// __launch_bounds__(256, 2) caps regs at 128 -> 2 CTAs/SM.
// ---------------------------------------------------------------------------
template<int MSTRIDE, int K, bool SPAN>
__global__ __launch_bounds__(256, 2)
void gemm_k(const float* __restrict__ A,
            const float* __restrict__ bias,
            const float* __restrict__ X)
{
    constexpr int BM = 128, BN = 128, BK = 32, TM = 8, TN = 8;
    __shared__ __align__(16) float As[BK][BM + 4];
    __shared__ __align__(16) float Bs[BK][BN];

    const int b   = blockIdx.z;
    const int n0  = blockIdx.x * BN;
    const int m0  = blockIdx.y * BM;
    const int tid = threadIdx.x;
    const int tx  = tid & 15;   // N dim
    const int ty  = tid >> 4;   // M dim

    const float* Bin  = SPAN ? (g_t    + (size_t)b * K * HWn) : (X   + (size_t)b * K * HWn);
    float*       Cout = SPAN ? (g_kern + (size_t)b * MSTRIDE * HWn) : (g_t + (size_t)b * MSTRIDE * HWn);

    ull acc2[TM][TN / 2] = {};   // [m][n-pair], packed {n, n+1}

    const int arow = tid >> 1;          // 0..127 (m within tile)
    const int ak   = (tid & 1) * 16;    // 0 or 16

    float4 aReg[4];
    float4 bReg[4];

    auto loadRegs = [&](int k0) {
        const float* ap = A + (size_t)(m0 + arow) * K + k0 + ak;
        #pragma unroll
        for (int i = 0; i < 4; i++)
            aReg[i] = *reinterpret_cast<const float4*>(ap + 4 * i);
        #pragma unroll
        for (int it = 0; it < 4; it++) {
            const int lin  = tid + it * 256;     // 0..1023
            const int brow = lin >> 5;           // 0..31
            const int bc4  = lin & 31;           // 0..31
            const int col  = n0 + bc4 * 4;
            float4 v;
            if (col < HWn) {
                v = *reinterpret_cast<const float4*>(Bin + (size_t)(k0 + brow) * HWn + col);
                if constexpr (SPAN) {
                    const int c   = k0 + brow;
                    const float sc = g_scale[c], sh = g_shift[c];
                    v.x = fmaxf(fmaf(v.x, sc, sh), 0.f);
                    v.y = fmaxf(fmaf(v.y, sc, sh), 0.f);
                    v.z = fmaxf(fmaf(v.z, sc, sh), 0.f);
                    v.w = fmaxf(fmaf(v.w, sc, sh), 0.f);
                }
            } else {
                v = make_float4(0.f, 0.f, 0.f, 0.f);
            }
            bReg[it] = v;
        }
    };
    auto storeSmem = [&]() {
        #pragma unroll
        for (int i = 0; i < 4; i++) {
            As[ak + 4 * i + 0][arow] = aReg[i].x;
            As[ak + 4 * i + 1][arow] = aReg[i].y;
            As[ak + 4 * i + 2][arow] = aReg[i].z;
            As[ak + 4 * i + 3][arow] = aReg[i].w;
        }
        #pragma unroll
        for (int it = 0; it < 4; it++) {
            const int lin  = tid + it * 256;
            const int brow = lin >> 5;
            const int bc4  = lin & 31;
            *reinterpret_cast<float4*>(&Bs[brow][bc4 * 4]) = bReg[it];
        }
    };

    loadRegs(0);
    storeSmem();
    __syncthreads();

    for (int k0 = 0; k0 < K; k0 += BK) {
        const bool more = (k0 + BK) < K;
        if (more) loadRegs(k0 + BK);   // LDGs overlap compute

        #pragma unroll 8
        for (int k = 0; k < BK; k++) {
            float4 a0 = *reinterpret_cast<const float4*>(&As[k][ty * TM]);
            float4 a1 = *reinterpret_cast<const float4*>(&As[k][ty * TM + 4]);
            ull ad[TM];
            ad[0] = dup2(a0.x); ad[1] = dup2(a0.y);
            ad[2] = dup2(a0.z); ad[3] = dup2(a0.w);
            ad[4] = dup2(a1.x); ad[5] = dup2(a1.y);
            ad[6] = dup2(a1.z); ad[7] = dup2(a1.w);
            const ull* bp = reinterpret_cast<const ull*>(&Bs[k][tx * TN]);
            ull b2[4];
            b2[0] = bp[0]; b2[1] = bp[1]; b2[2] = bp[2]; b2[3] = bp[3];
            #pragma unroll
            for (int i = 0; i < TM; i++)
                #pragma unroll
                for (int j = 0; j < TN / 2; j++)
                    fma2(acc2[i][j], ad[i], b2[j]);
        }

        if (more) {
            __syncthreads();
            storeSmem();
            __syncthreads();
        }
    }

    // ---- store (+bias) ----
    const int colb = n0 + tx * TN;
    if (colb < HWn) {
        #pragma unroll
        for (int i = 0; i < TM; i++) {
            const int grow = m0 + ty * TM + i;
            const float bv = bias[grow];
            float o[TN];
            #pragma unroll
            for (int j = 0; j < TN / 2; j++)
                unpack2(acc2[i][j], o[2 * j], o[2 * j + 1]);
            float4 o0, o1;
            o0.x = o[0] + bv; o0.y = o[1] + bv; o0.z = o[2] + bv; o0.w = o[3] + bv;
            o1.x = o[4] + bv; o1.y = o[5] + bv; o1.z = o[6] + bv; o1.w = o[7] + bv;
            float* cp = Cout + (size_t)grow * HWn + colb;
            *reinterpret_cast<float4*>(cp)     = o0;
            *reinterpret_cast<float4*>(cp + 4) = o1;
        }
    }
}

// ---------------------------------------------------------------------------
// Tail GEMM for span rows 128..143 (16 rows). All 16 warps live, TM=1.
//   g_kern[b][128+ty][n] = sum_k w_span[128+ty][k] * relu(bn(g_t[b][k][n]))
// ---------------------------------------------------------------------------
__global__ __launch_bounds__(256)
void gemm_tail(const float* __restrict__ A,   // w_span
               const float* __restrict__ bias)
{
    constexpr int BN = 128, BK = 32, MR = 16, MOFF = 128, K = CRr;
    __shared__ __align__(16) float As[BK][MR];
    __shared__ __align__(16) float Bs[BK][BN];

    const int b   = blockIdx.z;
    const int n0  = blockIdx.x * BN;
    const int tid = threadIdx.x;
    const int tx  = tid & 15;   // N dim (8 cols)
    const int ty  = tid >> 4;   // M row (0..15)

    const float* Bin  = g_t    + (size_t)b * K * HWn;
    float*       Cout = g_kern + (size_t)b * KKGc * HWn;

    ull acc2[4] = {};

    // A staging: 16 rows x 32 k = 512 floats; each thread loads 2 (float2)
    const int arow = tid & 15;
    const int ak   = (tid >> 4) * 2;

    for (int k0 = 0; k0 < K; k0 += BK) {
        {
            const float* ap = A + (size_t)(MOFF + arow) * K + k0 + ak;
            float2 v = *reinterpret_cast<const float2*>(ap);
            As[ak + 0][arow] = v.x;
            As[ak + 1][arow] = v.y;
        }
        #pragma unroll
        for (int it = 0; it < 4; it++) {
            const int lin  = tid + it * 256;
            const int brow = lin >> 5;
            const int bc4  = lin & 31;
            const int col  = n0 + bc4 * 4;
            float4 v;
            if (col < HWn) {
                v = *reinterpret_cast<const float4*>(Bin + (size_t)(k0 + brow) * HWn + col);
                const int c   = k0 + brow;
                const float sc = g_scale[c], sh = g_shift[c];
                v.x = fmaxf(fmaf(v.x, sc, sh), 0.f);
                v.y = fmaxf(fmaf(v.y, sc, sh), 0.f);
                v.z = fmaxf(fmaf(v.z, sc, sh), 0.f);
                v.w = fmaxf(fmaf(v.w, sc, sh), 0.f);
            } else {
                v = make_float4(0.f, 0.f, 0.f, 0.f);
            }
            *reinterpret_cast<float4*>(&Bs[brow][bc4 * 4]) = v;
        }
        __syncthreads();

        #pragma unroll 8
        for (int k = 0; k < BK; k++) {
            const ull a = dup2(As[k][ty]);
            const ull* bp = reinterpret_cast<const ull*>(&Bs[k][tx * 8]);
            fma2(acc2[0], a, bp[0]);
            fma2(acc2[1], a, bp[1]);
            fma2(acc2[2], a, bp[2]);
            fma2(acc2[3], a, bp[3]);
        }
        __syncthreads();
    }

    const int colb = n0 + tx * 8;
    if (colb < HWn) {
        const float bv = bias[MOFF + ty];
        float o[8];
        #pragma unroll
        for (int j = 0; j < 4; j++) unpack2(acc2[j], o[2 * j], o[2 * j + 1]);
        float4 o0, o1;
        o0.x = o[0] + bv; o0.y = o[1] + bv; o0.z = o[2] + bv; o0.w = o[3] + bv;
        o1.x = o[4] + bv; o1.y = o[5] + bv; o1.z = o[6] + bv; o1.w = o[7] + bv;
        float* cp = Cout + (size_t)(MOFF + ty) * HWn + colb;
        *reinterpret_cast<float4*>(cp)     = o0;
        *reinterpret_cast<float4*>(cp + 4) = o1;
    }
}

// ---------------------------------------------------------------------------
// BatchNorm stats, two-stage deterministic reduction.
// ---------------------------------------------------------------------------
__global__ __launch_bounds__(256)
void bn_partial()
{
    const int c   = blockIdx.x;
    const int b   = blockIdx.y;
    const int tid = threadIdx.x;
    const float4* p = reinterpret_cast<const float4*>(
        g_t + ((size_t)b * CRr + c) * HWn);
    float s = 0.f, sq = 0.f;
    for (int i = tid; i < HWn / 4; i += 256) {
        float4 v = p[i];
        s += v.x + v.y + v.z + v.w;
        sq = fmaf(v.x, v.x, sq); sq = fmaf(v.y, v.y, sq);
        sq = fmaf(v.z, v.z, sq); sq = fmaf(v.w, v.w, sq);
    }
    __shared__ float ss[256], sqs[256];
    ss[tid] = s; sqs[tid] = sq;
    __syncthreads();
    for (int o = 128; o > 0; o >>= 1) {
        if (tid < o) { ss[tid] += ss[tid + o]; sqs[tid] += sqs[tid + o]; }
        __syncthreads();
    }
    if (tid == 0) { g_bns[c][b] = ss[0]; g_bnq[c][b] = sqs[0]; }
}

__global__ __launch_bounds__(CRr)
void bn_finalize(const float* __restrict__ gamma, const float* __restrict__ beta)
{
    const int c = threadIdx.x;
    float s = 0.f, sq = 0.f;
    #pragma unroll
    for (int b = 0; b < BB; b++) { s += g_bns[c][b]; sq += g_bnq[c][b]; }
    const float inv  = 1.f / (float)(BB * HWn);
    const float mean = s * inv;
    const float var  = sq * inv - mean * mean;
    const float rstd = rsqrtf(var + 1e-5f);
    const float sc   = gamma[c] * rstd;
    g_scale[c] = sc;
    g_shift[c] = beta[c] - mean * sc;
}

// ---------------------------------------------------------------------------
// Involution gather (R7 structure — cheap staging indexing, taps from gmem).
// ---------------------------------------------------------------------------
#define THT 8
__global__ __launch_bounds__(448)
void involution_kernel(const float* __restrict__ x, float* __restrict__ out)
{
    __shared__ float sx[16][THT + 2][58];   // [d][row(halo)][col(halo)]

    const int h0  = blockIdx.x * THT;
    const int g   = blockIdx.y;
    const int b   = blockIdx.z;
    const int tid = threadIdx.x;            // 0..447

    const int w = tid % WWc;                // 0..55
    const int q = tid / WWc;                // 0..7

    const float* xg = x + ((size_t)b * C_IN + g * 16) * HWn;
    for (int p = tid; p < (THT + 2) * 58; p += 448) {
        const int r    = p / 58;
        const int cpos = p - r * 58;
        const int hh   = h0 - 1 + r;
        const int ww   = cpos - 1;
        const bool ok  = (hh >= 0) && (hh < HH) && (ww >= 0) && (ww < WWc);
        const float* src = xg + hh * WWc + ww;
        #pragma unroll
        for (int d = 0; d < 16; d++)
            sx[d][r][cpos] = ok ? src[(size_t)d * HWn] : 0.f;
    }

    const float* kg = g_kern + ((size_t)b * KKGc + g) * HWn + (h0 + q) * WWc + w;
    float kv[9];
    #pragma unroll
    for (int t = 0; t < 9; t++) kv[t] = kg[(size_t)t * 16 * HWn];

    __syncthreads();

    float* og = out + ((size_t)b * C_IN + g * 16) * HWn + (h0 + q) * WWc + w;
    #pragma unroll
    for (int d = 0; d < 16; d++) {
        float acc = 0.f;
        #pragma unroll
        for (int i = 0; i < 3; i++)
            #pragma unroll
            for (int j = 0; j < 3; j++)
                acc = fmaf(sx[d][q + i][w + j], kv[i * 3 + j], acc);
        og[(size_t)d * HWn] = acc;
    }
}

// ---------------------------------------------------------------------------
extern "C" void kernel_launch(void* const* d_in, const int* in_sizes, int n_in,
                              void* d_out, int out_size)
{
    (void)in_sizes; (void)n_in; (void)out_size;
    const float* x        = (const float*)d_in[0];
    const float* w_reduce = (const float*)d_in[1];
    const float* b_reduce = (const float*)d_in[2];
    const float* gamma    = (const float*)d_in[3];
    const float* beta     = (const float*)d_in[4];
    const float* w_span   = (const float*)d_in[5];
    const float* b_span   = (const float*)d_in[6];
    float* out = (float*)d_out;

    // 1) reduce conv:  t = w_reduce @ x + b_reduce     (M=128, K=256)
    dim3 g1((HWn + 127) / 128, 1, BB);
    gemm_k<CRr, C_IN, false><<<g1, 256>>>(w_reduce, b_reduce, x);

    // 2) BN batch statistics -> folded scale/shift (two-stage, deterministic)
    bn_partial<<<dim3(CRr, BB), 256>>>();
    bn_finalize<<<1, CRr>>>(gamma, beta);

    // 3) span conv rows 0..127 (clean M=128) + rows 128..143 (tail kernel)
    dim3 g2((HWn + 127) / 128, 1, BB);
    gemm_k<KKGc, CRr, true><<<g2, 256>>>(w_span, b_span, nullptr);
    gemm_tail<<<dim3((HWn + 127) / 128, 1, BB), 256>>>(w_span, b_span);

    // 4) involution gather
    dim3 g3(HH / THT, 16, BB);
    involution_kernel<<<g3, 448>>>(x, out);
}

// round 10
// speedup vs baseline: 2.8061x; 1.1970x over previous
#include <cuda_runtime.h>
#include <cuda_bf16.h>
#include <cstdint>

#define BB   16
#define C_IN 256
#define CRr  128
#define KKGc 144
#define HWn  3136
#define HH   56
#define WWc  56

typedef unsigned long long ull;

// ---------------- scratch (allocation-free: __device__ globals) ----------------
__device__ float g_t[(size_t)BB * CRr * HWn];     // reduce-conv output  [b][cr][hw]
__device__ float g_kern[(size_t)BB * KKGc * HWn]; // span-conv output    [b][o][hw]
__device__ float g_scale[CRr];
__device__ float g_shift[CRr];
__device__ float g_bns[CRr][BB];
__device__ float g_bnq[CRr][BB];

// A-fragment arrays (mma layout), [kstep][mtile][lane] -> uint4 (a0..a3)
__device__ uint4 g_af1h[16 * 8 * 32], g_af1l[16 * 8 * 32];   // w_reduce 128x256
__device__ uint4 g_af2h[8 * 9 * 32],  g_af2l[8 * 9 * 32];    // w_span  144x128

// ---------------- helpers ----------------
// pack two f32 -> bf16x2 (lo half = e0)
__device__ __forceinline__ uint32_t packbf(float e0, float e1) {
    uint32_t r;
    asm("cvt.rn.bf16x2.f32 %0, %1, %2;" : "=r"(r) : "f"(e1), "f"(e0));
    return r;
}
__device__ __forceinline__ float bf_lo(uint32_t h) { return __uint_as_float(h << 16); }
__device__ __forceinline__ float bf_hi(uint32_t h) { return __uint_as_float(h & 0xFFFF0000u); }

__device__ __forceinline__ void mma_bf16(float* c, const uint4& a,
                                         uint32_t b0, uint32_t b1) {
    asm volatile(
        "mma.sync.aligned.m16n8k16.row.col.f32.bf16.bf16.f32 "
        "{%0,%1,%2,%3}, {%4,%5,%6,%7}, {%8,%9}, {%0,%1,%2,%3};"
        : "+f"(c[0]), "+f"(c[1]), "+f"(c[2]), "+f"(c[3])
        : "r"(a.x), "r"(a.y), "r"(a.z), "r"(a.w), "r"(b0), "r"(b1));
}

// ---------------------------------------------------------------------------
// Prep: convert weight matrix W [M x ldk] into mma A-fragments (hi/lo bf16).
// Block = one (kstep, mtile); 32 threads (one warp).
// Frag layout (m16n8k16 row-major A): g = lane>>2, tc = lane&3;
//   a0 = {A[g][tc2], A[g][tc2+1]}   a1 = {A[g+8][tc2], ...}
//   a2 = {A[g][tc2+8], ...}         a3 = {A[g+8][tc2+8], ...}
// ---------------------------------------------------------------------------
__global__ void prep_afrag(const float* __restrict__ W,
                           uint4* __restrict__ hi, uint4* __restrict__ lo,
                           int MT, int ldk)
{
    const int blk  = blockIdx.x;          // kstep*MT + mt
    const int mt   = blk % MT;
    const int ks   = blk / MT;
    const int lane = threadIdx.x;
    const int g    = lane >> 2;
    const int tc2  = (lane & 3) * 2;
    const float* w0 = W + (size_t)(mt * 16 + g)     * ldk + ks * 16 + tc2;
    const float* w1 = W + (size_t)(mt * 16 + g + 8) * ldk + ks * 16 + tc2;

    const float a00 = w0[0], a01 = w0[1], a08 = w0[8], a09 = w0[9];
    const float b00 = w1[0], b01 = w1[1], b08 = w1[8], b09 = w1[9];

    uint4 H, L;
    H.x = packbf(a00, a01); H.y = packbf(b00, b01);
    H.z = packbf(a08, a09); H.w = packbf(b08, b09);
    L.x = packbf(a00 - bf_lo(H.x), a01 - bf_hi(H.x));
    L.y = packbf(b00 - bf_lo(H.y), b01 - bf_hi(H.y));
    L.z = packbf(a08 - bf_lo(H.z), a09 - bf_hi(H.z));
    L.w = packbf(b08 - bf_lo(H.w), b09 - bf_hi(H.w));

    hi[blk * 32 + lane] = H;
    lo[blk * 32 + lane] = L;
}

// ---------------------------------------------------------------------------
// Tensor-core GEMM via mma.sync bf16, 3-pass split (hh + hl + lh), fp32 acc.
//   C[m][n] = sum_k A[m][k] * Bin[k][n] + bias[m]
// MT m16-tiles (8 -> M=128, 9 -> M=144), BN=112 (28 tiles over HWn), BK=32.
// SPAN: Bin = relu(g_t*scale+shift) -> g_kern; else Bin = x -> g_t.
// 224 threads = 7 warps, each warp owns 16 output columns.
// ---------------------------------------------------------------------------
template<int MT, int K, bool SPAN>
__global__ __launch_bounds__(224, 2)
void gemm_mma(const uint4* __restrict__ afh, const uint4* __restrict__ afl,
              const float* __restrict__ bias, const float* __restrict__ X)
{
    constexpr int KT = K / 32;
    __shared__ uint4 sAh[2 * MT * 32], sAl[2 * MT * 32];
    __shared__ uint16_t sBh[112][34], sBl[112][34];   // [n][k], pad->odd words

    const int tid  = threadIdx.x;
    const int wid  = tid >> 5;            // 0..6
    const int lane = tid & 31;
    const int n0   = blockIdx.x * 112;
    const int b    = blockIdx.z;

    const float* Bin = SPAN ? (g_t + (size_t)b * K * HWn)
                            : (X   + (size_t)b * K * HWn);
    float* Cout = SPAN ? (g_kern + (size_t)b * KKGc * HWn)
                       : (g_t    + (size_t)b * CRr  * HWn);

    float acc[MT][8] = {};

    const int g   = lane >> 2;
    const int tc2 = (lane & 3) * 2;
    const int nw  = wid * 16;

    for (int kt = 0; kt < KT; kt++) {
        if (kt) __syncthreads();          // previous tile fully consumed

        // ---- stage A frags for 2 ksteps (flat copy, coalesced) ----
        {
            const uint4* sh = afh + (size_t)(2 * kt) * MT * 32;
            const uint4* sl = afl + (size_t)(2 * kt) * MT * 32;
            for (int i = tid; i < 2 * MT * 32; i += 224) {
                sAh[i] = sh[i];
                sAl[i] = sl[i];
            }
        }
        // ---- stage B tile [32 k][112 n] -> bf16 hi/lo [n][k] ----
        const int kb = kt * 32;
        #pragma unroll
        for (int p = 0; p < 16; p++) {
            const int idx = tid + p * 224;      // 0..3583
            const int k   = idx / 112;
            const int n   = idx - k * 112;
            float v = Bin[(size_t)(kb + k) * HWn + n0 + n];
            if constexpr (SPAN)
                v = fmaxf(fmaf(v, g_scale[kb + k], g_shift[kb + k]), 0.f);
            const __nv_bfloat16 h = __float2bfloat16(v);
            const __nv_bfloat16 l = __float2bfloat16(v - __bfloat162float(h));
            sBh[n][k] = __bfloat16_as_ushort(h);
            sBl[n][k] = __bfloat16_as_ushort(l);
        }
        __syncthreads();

        // ---- compute: 2 ksteps x MT mtiles x 2 ntiles x 3 passes ----
        #pragma unroll
        for (int s = 0; s < 2; s++) {
            uint32_t bh0[2], bh1[2], bl0[2], bl1[2];
            #pragma unroll
            for (int t = 0; t < 2; t++) {
                const int n  = nw + t * 8 + g;
                const int kk = s * 16 + tc2;
                bh0[t] = *reinterpret_cast<const uint32_t*>(&sBh[n][kk]);
                bh1[t] = *reinterpret_cast<const uint32_t*>(&sBh[n][kk + 8]);
                bl0[t] = *reinterpret_cast<const uint32_t*>(&sBl[n][kk]);
                bl1[t] = *reinterpret_cast<const uint32_t*>(&sBl[n][kk + 8]);
            }
            #pragma unroll
            for (int m = 0; m < MT; m++) {
                const uint4 ah = sAh[(s * MT + m) * 32 + lane];
                const uint4 al = sAl[(s * MT + m) * 32 + lane];
                #pragma unroll
                for (int t = 0; t < 2; t++) {
                    mma_bf16(&acc[m][t * 4], ah, bh0[t], bh1[t]);
                    mma_bf16(&acc[m][t * 4], ah, bl0[t], bl1[t]);
                    mma_bf16(&acc[m][t * 4], al, bh0[t], bh1[t]);
                }
            }
        }
    }

    // ---- epilogue: +bias, fp32 stores (float2) ----
    #pragma unroll
    for (int m = 0; m < MT; m++) {
        const int r1 = m * 16 + g, r2 = r1 + 8;
        const float bv1 = bias[r1], bv2 = bias[r2];
        #pragma unroll
        for (int t = 0; t < 2; t++) {
            const int col = n0 + nw + t * 8 + tc2;
            float2 o1 = make_float2(acc[m][t * 4 + 0] + bv1,
                                    acc[m][t * 4 + 1] + bv1);
            float2 o2 = make_float2(acc[m][t * 4 + 2] + bv2,
                                    acc[m][t * 4 + 3] + bv2);
            *reinterpret_cast<float2*>(Cout + (size_t)r1 * HWn + col) = o1;
            *reinterpret_cast<float2*>(Cout + (size_t)r2 * HWn + col) = o2;
        }
    }
}

// ---------------------------------------------------------------------------
// BatchNorm stats, two-stage deterministic reduction.
// ---------------------------------------------------------------------------
__global__ __launch_bounds__(256)
void bn_partial()
{
    const int c   = blockIdx.x;
    const int b   = blockIdx.y;
    const int tid = threadIdx.x;
    const float4* p = reinterpret_cast<const float4*>(
        g_t + ((size_t)b * CRr + c) * HWn);
    float s = 0.f, sq = 0.f;
    for (int i = tid; i < HWn / 4; i += 256) {
        float4 v = p[i];
        s += v.x + v.y + v.z + v.w;
        sq = fmaf(v.x, v.x, sq); sq = fmaf(v.y, v.y, sq);
        sq = fmaf(v.z, v.z, sq); sq = fmaf(v.w, v.w, sq);
    }
    __shared__ float ss[256], sqs[256];
    ss[tid] = s; sqs[tid] = sq;
    __syncthreads();
    for (int o = 128; o > 0; o >>= 1) {
        if (tid < o) { ss[tid] += ss[tid + o]; sqs[tid] += sqs[tid + o]; }
        __syncthreads();
    }
    if (tid == 0) { g_bns[c][b] = ss[0]; g_bnq[c][b] = sqs[0]; }
}

__global__ __launch_bounds__(CRr)
void bn_finalize(const float* __restrict__ gamma, const float* __restrict__ beta)
{
    const int c = threadIdx.x;
    float s = 0.f, sq = 0.f;
    #pragma unroll
    for (int b = 0; b < BB; b++) { s += g_bns[c][b]; sq += g_bnq[c][b]; }
    const float inv  = 1.f / (float)(BB * HWn);
    const float mean = s * inv;
    const float var  = sq * inv - mean * mean;
    const float rstd = rsqrtf(var + 1e-5f);
    const float sc   = gamma[c] * rstd;
    g_scale[c] = sc;
    g_shift[c] = beta[c] - mean * sc;
}

// ---------------------------------------------------------------------------
// Involution gather (R8 structure — proven).
// ---------------------------------------------------------------------------
#define THT 8
__global__ __launch_bounds__(448)
void involution_kernel(const float* __restrict__ x, float* __restrict__ out)
{
    __shared__ float sx[16][THT + 2][58];

    const int h0  = blockIdx.x * THT;
    const int g   = blockIdx.y;
    const int b   = blockIdx.z;
    const int tid = threadIdx.x;

    const int w = tid % WWc;
    const int q = tid / WWc;

    const float* xg = x + ((size_t)b * C_IN + g * 16) * HWn;
    for (int p = tid; p < (THT + 2) * 58; p += 448) {
        const int r    = p / 58;
        const int cpos = p - r * 58;
        const int hh   = h0 - 1 + r;
        const int ww   = cpos - 1;
        const bool ok  = (hh >= 0) && (hh < HH) && (ww >= 0) && (ww < WWc);
        const float* src = xg + hh * WWc + ww;
        #pragma unroll
        for (int d = 0; d < 16; d++)
            sx[d][r][cpos] = ok ? src[(size_t)d * HWn] : 0.f;
    }

    const float* kg = g_kern + ((size_t)b * KKGc + g) * HWn + (h0 + q) * WWc + w;
    float kv[9];
    #pragma unroll
    for (int t = 0; t < 9; t++) kv[t] = kg[(size_t)t * 16 * HWn];

    __syncthreads();

    float* og = out + ((size_t)b * C_IN + g * 16) * HWn + (h0 + q) * WWc + w;
    #pragma unroll
    for (int d = 0; d < 16; d++) {
        float acc = 0.f;
        #pragma unroll
        for (int i = 0; i < 3; i++)
            #pragma unroll
            for (int j = 0; j < 3; j++)
                acc = fmaf(sx[d][q + i][w + j], kv[i * 3 + j], acc);
        og[(size_t)d * HWn] = acc;
    }
}

// ---------------------------------------------------------------------------
extern "C" void kernel_launch(void* const* d_in, const int* in_sizes, int n_in,
                              void* d_out, int out_size)
{
    (void)in_sizes; (void)n_in; (void)out_size;
    const float* x        = (const float*)d_in[0];
    const float* w_reduce = (const float*)d_in[1];
    const float* b_reduce = (const float*)d_in[2];
    const float* gamma    = (const float*)d_in[3];
    const float* beta     = (const float*)d_in[4];
    const float* w_span   = (const float*)d_in[5];
    const float* b_span   = (const float*)d_in[6];
    float* out = (float*)d_out;

    uint4 *af1h, *af1l, *af2h, *af2l;
    cudaGetSymbolAddress((void**)&af1h, g_af1h);
    cudaGetSymbolAddress((void**)&af1l, g_af1l);
    cudaGetSymbolAddress((void**)&af2h, g_af2h);
    cudaGetSymbolAddress((void**)&af2l, g_af2l);

    // 0) weight fragment prep (tiny)
    prep_afrag<<<16 * 8, 32>>>(w_reduce, af1h, af1l, 8, C_IN);
    prep_afrag<<<8 * 9, 32>>>(w_span,   af2h, af2l, 9, CRr);

    // 1) reduce conv (mma.sync bf16 3-pass): t = w_reduce @ x + b_reduce
    gemm_mma<8, C_IN, false><<<dim3(HWn / 112, 1, BB), 224>>>(af1h, af1l, b_reduce, x);

    // 2) BN batch statistics -> folded scale/shift
    bn_partial<<<dim3(CRr, BB), 256>>>();
    bn_finalize<<<1, CRr>>>(gamma, beta);

    // 3) span conv, all 144 rows in one kernel (9 m-tiles)
    gemm_mma<9, CRr, true><<<dim3(HWn / 112, 1, BB), 224>>>(af2h, af2l, b_span, nullptr);

    // 4) involution gather
    dim3 g3(HH / THT, 16, BB);
    involution_kernel<<<g3, 448>>>(x, out);
}